// round 11
// baseline (speedup 1.0000x reference)
#include <cuda_runtime.h>
#include <cuda_bf16.h>

typedef unsigned int u32;
typedef unsigned long long ull;

#define HW   96
#define TPB  384
#define LDB  104              // bf16 elems per tile row (stride 208 B, conflict-free ldmatrix)
#define RSB  (LDB * 2)        // 208 bytes
#define TILE_B (HW * RSB)     // 19968 B per tile

// ---- smem byte offsets ----
#define OFF_KH   0            // 13 floats
#define OFF_KW   64           // 13 floats
#define T_BASE   128
#define T_QH   (T_BASE + 0 * TILE_B)
#define T_QL   (T_BASE + 1 * TILE_B)
#define T_KH   (T_BASE + 2 * TILE_B)
#define T_KL   (T_BASE + 3 * TILE_B)
#define T_VH   (T_BASE + 4 * TILE_B)
#define T_VL   (T_BASE + 5 * TILE_B)
#define T_A1H  (T_BASE + 6 * TILE_B)
#define T_A1L  (T_BASE + 7 * TILE_B)
#define T_A2H  (T_BASE + 8 * TILE_B)
#define T_A2L  (T_BASE + 9 * TILE_B)
#define SMEM_TOTAL (T_BASE + 10 * TILE_B)   // 199808 B
// Out-partial buffer overlays A1 (dead after P2): 6 pairs x 16 rows x 104 f32
#define PART      T_A1H
#define PART_RS   416                        // bytes per row (104 floats)
#define PART_PAIR (16 * PART_RS)             // 6656 B; 6 pairs = 39936 = 2*TILE_B

// ---------------- PTX wrappers ----------------
__device__ __forceinline__ u32 s2u(const void* p) {
    u32 a;
    asm("{ .reg .u64 t; cvta.to.shared.u64 t, %1; cvt.u32.u64 %0, t; }" : "=r"(a) : "l"(p));
    return a;
}
template<int TR>
__device__ __forceinline__ void ldsm4(u32 addr, u32* r) {
    if (TR)
        asm volatile("ldmatrix.sync.aligned.m8n8.x4.trans.shared.b16 {%0,%1,%2,%3}, [%4];"
                     : "=r"(r[0]), "=r"(r[1]), "=r"(r[2]), "=r"(r[3]) : "r"(addr));
    else
        asm volatile("ldmatrix.sync.aligned.m8n8.x4.shared.b16 {%0,%1,%2,%3}, [%4];"
                     : "=r"(r[0]), "=r"(r[1]), "=r"(r[2]), "=r"(r[3]) : "r"(addr));
}
__device__ __forceinline__ void mma16816(float* c, const u32* a, const u32* b) {
    asm volatile("mma.sync.aligned.m16n8k16.row.col.f32.bf16.bf16.f32 "
                 "{%0,%1,%2,%3}, {%4,%5,%6,%7}, {%8,%9}, {%0,%1,%2,%3};"
                 : "+f"(c[0]), "+f"(c[1]), "+f"(c[2]), "+f"(c[3])
                 : "r"(a[0]), "r"(a[1]), "r"(a[2]), "r"(a[3]), "r"(b[0]), "r"(b[1]));
}
#define BAR_ARRIVE(id) asm volatile("bar.arrive %0, 64;" :: "r"(id) : "memory")
#define BAR_SYNC(id)   asm volatile("bar.sync %0, 64;"   :: "r"(id) : "memory")

// ---- hi/lo bf16 split: pack pair (x0,x1) -> hi u32, lo u32 ----
__device__ __forceinline__ void cvt2(float x0, float x1, u32& h, u32& l) {
    asm("cvt.rn.bf16x2.f32 %0, %1, %2;" : "=r"(h) : "f"(x1), "f"(x0));
    float h0 = __uint_as_float(h << 16);
    float h1 = __uint_as_float(h & 0xffff0000u);
    asm("cvt.rn.bf16x2.f32 %0, %1, %2;" : "=r"(l) : "f"(x1 - h1), "f"(x0 - h0));
}

// ---------------- warp-tile GEMM: 16 x (8*NT) x 96, BF16x3 split ----------------
template<int TA, int TB, int NT>
__device__ __forceinline__ void gemm_wt(float acc[NT][4],
                                        u32 aH, u32 aL, u32 bH, u32 bL,
                                        int m0, int n0, int lane)
{
    #pragma unroll
    for (int nt = 0; nt < NT; nt++)
        #pragma unroll
        for (int e = 0; e < 4; e++) acc[nt][e] = 0.f;

    u32 aad;
    {
        int ra, ca;
        if (TA) { ra = (lane & 7) + ((lane >> 4) & 1) * 8; ca = m0 + ((lane >> 3) & 1) * 8; }
        else    { ra = m0 + (lane & 7) + ((lane >> 3) & 1) * 8; ca = ((lane >> 4) & 1) * 8; }
        aad = (u32)(ra * RSB + ca * 2);
    }
    const u32 astep = TA ? (u32)(16 * RSB) : 32u;

    u32 bad[NT / 2];
    #pragma unroll
    for (int p = 0; p < NT / 2; p++) {
        int rb, cb;
        if (TB) { rb = (lane & 7) + ((lane >> 3) & 1) * 8; cb = n0 + p * 16 + ((lane >> 4) & 1) * 8; }
        else    { rb = n0 + p * 16 + (lane & 7) + ((lane >> 4) & 1) * 8; cb = ((lane >> 3) & 1) * 8; }
        bad[p] = (u32)(rb * RSB + cb * 2);
    }
    const u32 bstep = TB ? (u32)(16 * RSB) : 32u;

    #pragma unroll
    for (int kk = 0; kk < HW; kk += 16) {
        u32 Ah[4], Al[4];
        ldsm4<TA>(aH + aad, Ah);
        ldsm4<TA>(aL + aad, Al);

        u32 Bh[NT][2], Bl[NT][2];
        #pragma unroll
        for (int p = 0; p < NT / 2; p++) {
            u32 t[4];
            ldsm4<TB>(bH + bad[p], t);
            Bh[2 * p][0] = t[0]; Bh[2 * p][1] = t[1];
            Bh[2 * p + 1][0] = t[2]; Bh[2 * p + 1][1] = t[3];
        }
        #pragma unroll
        for (int nt = 0; nt < NT; nt++) mma16816(acc[nt], Ah, Bh[nt]);
        #pragma unroll
        for (int p = 0; p < NT / 2; p++) {
            u32 t[4];
            ldsm4<TB>(bL + bad[p], t);
            Bl[2 * p][0] = t[0]; Bl[2 * p][1] = t[1];
            Bl[2 * p + 1][0] = t[2]; Bl[2 * p + 1][1] = t[3];
        }
        #pragma unroll
        for (int nt = 0; nt < NT; nt++) mma16816(acc[nt], Al, Bh[nt]);
        #pragma unroll
        for (int nt = 0; nt < NT; nt++) mma16816(acc[nt], Ah, Bl[nt]);

        aad += astep;
        #pragma unroll
        for (int p = 0; p < NT / 2; p++) bad[p] += bstep;
    }
}

__global__ void __launch_bounds__(TPB, 1)
axial_attn_hmma4(const float* __restrict__ gq, const float* __restrict__ gk,
                 const float* __restrict__ gv, const float* __restrict__ gkh,
                 const float* __restrict__ gkw, float* __restrict__ gout, int C)
{
    extern __shared__ char sm[];
    const u32 sb = s2u(sm);
    const int tid  = threadIdx.x;
    const int lane = tid & 31;
    const int wid  = tid >> 5;        // 0..11
    const int pair = (wid < 6) ? wid : wid - 6;   // 0..5
    const int m0   = pair * 16;

    const int slice = blockIdx.x;
    const int c = slice - (slice / C) * C;
    const size_t base = (size_t)slice * (HW * HW);

    if (tid < 13) {
        ((float*)(sm + OFF_KH))[tid] = gkh[c * 13 + tid];
        ((float*)(sm + OFF_KW))[tid] = gkw[c * 13 + tid];
    }

    // ---- load + hi/lo convert Q, K, V (row-major, stride 104 bf16) ----
    const float4* q4 = (const float4*)(gq + base);
    const float4* k4 = (const float4*)(gk + base);
    const float4* v4 = (const float4*)(gv + base);
    #pragma unroll
    for (int it = 0; it < 6; it++) {
        int idx = tid + it * TPB;               // 0..2303
        int r   = idx / 24;
        int c4  = (idx - r * 24) * 4;
        u32 ad  = (u32)(r * RSB + c4 * 2);
        u32 h0, l0, h1, l1;
        float4 x;
        x = q4[idx];
        cvt2(x.x, x.y, h0, l0); cvt2(x.z, x.w, h1, l1);
        *(ull*)(sm + T_QH + ad) = (ull)h0 | ((ull)h1 << 32);
        *(ull*)(sm + T_QL + ad) = (ull)l0 | ((ull)l1 << 32);
        x = k4[idx];
        cvt2(x.x, x.y, h0, l0); cvt2(x.z, x.w, h1, l1);
        *(ull*)(sm + T_KH + ad) = (ull)h0 | ((ull)h1 << 32);
        *(ull*)(sm + T_KL + ad) = (ull)l0 | ((ull)l1 << 32);
        x = v4[idx];
        cvt2(x.x, x.y, h0, l0); cvt2(x.z, x.w, h1, l1);
        *(ull*)(sm + T_VH + ad) = (ull)h0 | ((ull)h1 << 32);
        *(ull*)(sm + T_VL + ad) = (ull)l0 | ((ull)l1 << 32);
    }
    __syncthreads();

    // ============ Phase 1: warps 0-5 -> A1 rows; warps 6-11 -> A2 rows =======
    {
        float acc1[12][4];
        const float* band;
        u32 dH, dL;
        if (wid < 6) {
            gemm_wt<0, 0, 12>(acc1, sb + T_QH, sb + T_QL, sb + T_KH, sb + T_KL, m0, 0, lane);
            band = (const float*)(sm + OFF_KH);
            dH = sb + T_A1H; dL = sb + T_A1L;
        } else {
            gemm_wt<1, 1, 12>(acc1, sb + T_QH, sb + T_QL, sb + T_KH, sb + T_KL, m0, 0, lane);
            band = (const float*)(sm + OFF_KW);
            dH = sb + T_A2H; dL = sb + T_A2L;
        }
        #pragma unroll
        for (int rh = 0; rh < 2; rh++) {
            const int row = m0 + (lane >> 2) + 8 * rh;
            float mx = -1e30f;
            #pragma unroll
            for (int nt = 0; nt < 12; nt++)
                mx = fmaxf(mx, fmaxf(acc1[nt][2 * rh], acc1[nt][2 * rh + 1]));
            mx = fmaxf(mx, __shfl_xor_sync(0xffffffffu, mx, 1));
            mx = fmaxf(mx, __shfl_xor_sync(0xffffffffu, mx, 2));
            float s = 0.f;
            #pragma unroll
            for (int nt = 0; nt < 12; nt++)
                #pragma unroll
                for (int e = 0; e < 2; e++) {
                    float ev = __expf(acc1[nt][2 * rh + e] - mx);
                    acc1[nt][2 * rh + e] = ev;
                    s += ev;
                }
            s += __shfl_xor_sync(0xffffffffu, s, 1);
            s += __shfl_xor_sync(0xffffffffu, s, 2);
            const float inv = 1.0f / s;
            #pragma unroll
            for (int nt = 0; nt < 12; nt++) {
                const int col = nt * 8 + (lane & 3) * 2;
                u32 b0 = (u32)(col - row + 6), b1 = (u32)(col + 1 - row + 6);
                float x0 = fmaf(acc1[nt][2 * rh + 0], inv, b0 < 13u ? band[b0] : 0.f);
                float x1 = fmaf(acc1[nt][2 * rh + 1], inv, b1 < 13u ? band[b1] : 0.f);
                u32 h, l;
                cvt2(x0, x1, h, l);
                const u32 ad = (u32)(row * RSB + col * 2);
                *(u32*)((char*)sm + (dH - sb) + ad) = h;
                *(u32*)((char*)sm + (dL - sb) + ad) = l;
            }
        }
    }

    // pair handoff: A1 rows (from warp `pair`) -> warp `pair+6`
    if (wid < 6) { __syncwarp(); BAR_ARRIVE(pair + 1); }
    else         { BAR_SYNC(pair + 1); }

    // ============ Phase 2: V1 rows m0, col-half per pair side (kept in regs) =
    // V1[i][w] = sum_j A1[i][j] V[j][w] : A=A1 norm (own rows), B=V trans
    const int n0b = (wid < 6) ? 0 : 48;
    float acc2[6][4];
    gemm_wt<0, 1, 6>(acc2, sb + T_A1H, sb + T_A1L, sb + T_VH, sb + T_VL, m0, n0b, lane);

    __syncthreads();   // A2 complete everywhere; A1 reads complete (PART overlay safe)

    // ============ Phase 3: Out rows m0 = V1(regs) @ A2^T, k-half per side ====
    // Out[h][w'] = sum_w V1[h][w] A2[w'][w] : A from acc2 (cvt in-register), B=A2 norm
    float acc3[12][4];
    {
        #pragma unroll
        for (int nt = 0; nt < 12; nt++)
            #pragma unroll
            for (int e = 0; e < 4; e++) acc3[nt][e] = 0.f;

        const int kh0 = n0b;   // this side's k-range within w
        u32 bad[6];
        #pragma unroll
        for (int p = 0; p < 6; p++) {
            int rb = p * 16 + (lane & 7) + ((lane >> 4) & 1) * 8;
            int cb = kh0 + ((lane >> 3) & 1) * 8;
            bad[p] = (u32)(rb * RSB + cb * 2);
        }
        const u32 bH = sb + T_A2H, bL = sb + T_A2L;

        #pragma unroll
        for (int s = 0; s < 3; s++) {
            u32 Ah[4], Al[4];
            cvt2(acc2[2 * s][0],     acc2[2 * s][1],     Ah[0], Al[0]);
            cvt2(acc2[2 * s][2],     acc2[2 * s][3],     Ah[1], Al[1]);
            cvt2(acc2[2 * s + 1][0], acc2[2 * s + 1][1], Ah[2], Al[2]);
            cvt2(acc2[2 * s + 1][2], acc2[2 * s + 1][3], Ah[3], Al[3]);

            u32 Bh[12][2], Bl[12][2];
            #pragma unroll
            for (int p = 0; p < 6; p++) {
                u32 t[4];
                ldsm4<0>(bH + bad[p], t);
                Bh[2 * p][0] = t[0]; Bh[2 * p][1] = t[1];
                Bh[2 * p + 1][0] = t[2]; Bh[2 * p + 1][1] = t[3];
            }
            #pragma unroll
            for (int nt = 0; nt < 12; nt++) mma16816(acc3[nt], Ah, Bh[nt]);
            #pragma unroll
            for (int p = 0; p < 6; p++) {
                u32 t[4];
                ldsm4<0>(bL + bad[p], t);
                Bl[2 * p][0] = t[0]; Bl[2 * p][1] = t[1];
                Bl[2 * p + 1][0] = t[2]; Bl[2 * p + 1][1] = t[3];
            }
            #pragma unroll
            for (int nt = 0; nt < 12; nt++) mma16816(acc3[nt], Al, Bh[nt]);
            #pragma unroll
            for (int nt = 0; nt < 12; nt++) mma16816(acc3[nt], Ah, Bl[nt]);

            #pragma unroll
            for (int p = 0; p < 6; p++) bad[p] += 32u;
        }
    }

    // ---- pair partial-sum: k-half 48-95 side stores, 0-47 side adds + gmem --
    if (wid >= 6) {
        char* pb = (char*)sm + PART + pair * PART_PAIR;
        #pragma unroll
        for (int rh = 0; rh < 2; rh++) {
            const int rl = (lane >> 2) + 8 * rh;
            #pragma unroll
            for (int nt = 0; nt < 12; nt++) {
                const int col = nt * 8 + (lane & 3) * 2;
                *(float2*)(pb + rl * PART_RS + col * 4) =
                    make_float2(acc3[nt][2 * rh + 0], acc3[nt][2 * rh + 1]);
            }
        }
        __syncwarp();
        BAR_ARRIVE(pair + 7);
    } else {
        BAR_SYNC(pair + 7);
        const char* pb = (const char*)sm + PART + pair * PART_PAIR;
        float* op = gout + base;
        #pragma unroll
        for (int rh = 0; rh < 2; rh++) {
            const int rl = (lane >> 2) + 8 * rh;
            const int row = m0 + rl;
            #pragma unroll
            for (int nt = 0; nt < 12; nt++) {
                const int col = nt * 8 + (lane & 3) * 2;
                float2 p = *(const float2*)(pb + rl * PART_RS + col * 4);
                *(float2*)(op + row * HW + col) =
                    make_float2(acc3[nt][2 * rh + 0] + p.x,
                                acc3[nt][2 * rh + 1] + p.y);
            }
        }
    }
}

extern "C" void kernel_launch(void* const* d_in, const int* in_sizes, int n_in,
                              void* d_out, int out_size)
{
    const float* q  = (const float*)d_in[0];
    const float* k  = (const float*)d_in[1];
    const float* v  = (const float*)d_in[2];
    const float* kh = (const float*)d_in[3];
    const float* kw = (const float*)d_in[4];
    float* out = (float*)d_out;

    const int slices = in_sizes[0] / (HW * HW);   // B*C = 2048
    const int C      = in_sizes[3] / 13;          // 256

    cudaFuncSetAttribute(axial_attn_hmma4,
                         cudaFuncAttributeMaxDynamicSharedMemorySize, SMEM_TOTAL);
    axial_attn_hmma4<<<slices, TPB, SMEM_TOTAL>>>(q, k, v, kh, kw, out, C);
}

// round 13
// speedup vs baseline: 1.0961x; 1.0961x over previous
#include <cuda_runtime.h>
#include <cuda_bf16.h>

typedef unsigned int u32;
typedef unsigned long long ull;

#define HW   96
#define TPB  384
#define NSM  148              // persistent grid size
#define LDB  104              // bf16 elems per tile row (stride 208 B, conflict-free ldmatrix)
#define RSB  (LDB * 2)        // 208 bytes
#define TILE_B (HW * RSB)     // 19968 B per tile

// ---- smem byte offsets ----
#define OFF_KH   0            // 13 floats
#define OFF_KW   64           // 13 floats
#define T_BASE   128
#define T_QH   (T_BASE + 0 * TILE_B)
#define T_QL   (T_BASE + 1 * TILE_B)
#define T_KH   (T_BASE + 2 * TILE_B)
#define T_KL   (T_BASE + 3 * TILE_B)
#define T_VH   (T_BASE + 4 * TILE_B)
#define T_VL   (T_BASE + 5 * TILE_B)
#define T_A1H  (T_BASE + 6 * TILE_B)
#define T_A1L  (T_BASE + 7 * TILE_B)
#define T_A2H  (T_BASE + 8 * TILE_B)
#define T_A2L  (T_BASE + 9 * TILE_B)
#define SMEM_TOTAL (T_BASE + 10 * TILE_B)   // 199808 B
// V1 reuses Q tiles (Q dead after GEMM3):
#define T_V1H T_QH
#define T_V1L T_QL

// ---------------- PTX wrappers ----------------
__device__ __forceinline__ u32 s2u(const void* p) {
    u32 a;
    asm("{ .reg .u64 t; cvta.to.shared.u64 t, %1; cvt.u32.u64 %0, t; }" : "=r"(a) : "l"(p));
    return a;
}
template<int TR>
__device__ __forceinline__ void ldsm4(u32 addr, u32* r) {
    if (TR)
        asm volatile("ldmatrix.sync.aligned.m8n8.x4.trans.shared.b16 {%0,%1,%2,%3}, [%4];"
                     : "=r"(r[0]), "=r"(r[1]), "=r"(r[2]), "=r"(r[3]) : "r"(addr));
    else
        asm volatile("ldmatrix.sync.aligned.m8n8.x4.shared.b16 {%0,%1,%2,%3}, [%4];"
                     : "=r"(r[0]), "=r"(r[1]), "=r"(r[2]), "=r"(r[3]) : "r"(addr));
}
__device__ __forceinline__ void mma16816(float* c, const u32* a, const u32* b) {
    asm volatile("mma.sync.aligned.m16n8k16.row.col.f32.bf16.bf16.f32 "
                 "{%0,%1,%2,%3}, {%4,%5,%6,%7}, {%8,%9}, {%0,%1,%2,%3};"
                 : "+f"(c[0]), "+f"(c[1]), "+f"(c[2]), "+f"(c[3])
                 : "r"(a[0]), "r"(a[1]), "r"(a[2]), "r"(a[3]), "r"(b[0]), "r"(b[1]));
}
__device__ __forceinline__ void pref_l2(const void* p) {
    asm volatile("prefetch.global.L2 [%0];" :: "l"(p));
}

// ---- hi/lo bf16 split: pack pair (x0,x1) -> hi u32, lo u32 ----
__device__ __forceinline__ void cvt2(float x0, float x1, u32& h, u32& l) {
    asm("cvt.rn.bf16x2.f32 %0, %1, %2;" : "=r"(h) : "f"(x1), "f"(x0));
    float h0 = __uint_as_float(h << 16);
    float h1 = __uint_as_float(h & 0xffff0000u);
    asm("cvt.rn.bf16x2.f32 %0, %1, %2;" : "=r"(l) : "f"(x1 - h1), "f"(x0 - h0));
}

// ---------------- warp-tile GEMM: 16 x (8*NT) x 96, BF16x3 split ----------------
// acc += Ah*Bh + Al*Bh + Ah*Bl ; Bl ldsm latency hidden behind Al*Bh pass.
template<int TA, int TB, int NT>
__device__ __forceinline__ void gemm_wt(float acc[NT][4],
                                        u32 aH, u32 aL, u32 bH, u32 bL,
                                        int m0, int n0, int lane)
{
    #pragma unroll
    for (int nt = 0; nt < NT; nt++)
        #pragma unroll
        for (int e = 0; e < 4; e++) acc[nt][e] = 0.f;

    u32 aad;
    {
        int ra, ca;
        if (TA) { ra = (lane & 7) + ((lane >> 4) & 1) * 8; ca = m0 + ((lane >> 3) & 1) * 8; }
        else    { ra = m0 + (lane & 7) + ((lane >> 3) & 1) * 8; ca = ((lane >> 4) & 1) * 8; }
        aad = (u32)(ra * RSB + ca * 2);
    }
    const u32 astep = TA ? (u32)(16 * RSB) : 32u;

    u32 bad[NT / 2];
    #pragma unroll
    for (int p = 0; p < NT / 2; p++) {
        int rb, cb;
        if (TB) { rb = (lane & 7) + ((lane >> 3) & 1) * 8; cb = n0 + p * 16 + ((lane >> 4) & 1) * 8; }
        else    { rb = n0 + p * 16 + (lane & 7) + ((lane >> 4) & 1) * 8; cb = ((lane >> 3) & 1) * 8; }
        bad[p] = (u32)(rb * RSB + cb * 2);
    }
    const u32 bstep = TB ? (u32)(16 * RSB) : 32u;

    #pragma unroll
    for (int kk = 0; kk < HW; kk += 16) {
        u32 Ah[4], Al[4];
        ldsm4<TA>(aH + aad, Ah);
        ldsm4<TA>(aL + aad, Al);

        u32 Bh[NT][2], Bl[NT][2];
        #pragma unroll
        for (int p = 0; p < NT / 2; p++) {
            u32 t[4];
            ldsm4<TB>(bH + bad[p], t);
            Bh[2 * p][0] = t[0]; Bh[2 * p][1] = t[1];
            Bh[2 * p + 1][0] = t[2]; Bh[2 * p + 1][1] = t[3];
        }
        #pragma unroll
        for (int nt = 0; nt < NT; nt++) mma16816(acc[nt], Ah, Bh[nt]);
        #pragma unroll
        for (int p = 0; p < NT / 2; p++) {
            u32 t[4];
            ldsm4<TB>(bL + bad[p], t);
            Bl[2 * p][0] = t[0]; Bl[2 * p][1] = t[1];
            Bl[2 * p + 1][0] = t[2]; Bl[2 * p + 1][1] = t[3];
        }
        #pragma unroll
        for (int nt = 0; nt < NT; nt++) mma16816(acc[nt], Al, Bh[nt]);
        #pragma unroll
        for (int nt = 0; nt < NT; nt++) mma16816(acc[nt], Ah, Bl[nt]);

        aad += astep;
        #pragma unroll
        for (int p = 0; p < NT / 2; p++) bad[p] += bstep;
    }
}

__global__ void __launch_bounds__(TPB, 1)
axial_attn_hmma5(const float* __restrict__ gq, const float* __restrict__ gk,
                 const float* __restrict__ gv, const float* __restrict__ gkh,
                 const float* __restrict__ gkw, float* __restrict__ gout,
                 int C, int slices)
{
    extern __shared__ char sm[];
    const u32 sb = s2u(sm);
    const int tid  = threadIdx.x;
    const int lane = tid & 31;
    const int wid  = tid >> 5;        // 0..11

    // load-loop index math: 384 threads, 24 float4 per row -> row advances 16/iter
    const int lr0 = tid / 24;
    const int lc0 = (tid - lr0 * 24) * 4;
    const u32 lad0 = (u32)(lr0 * RSB + lc0 * 2);

    for (int s = blockIdx.x; s < slices; s += NSM) {
        const int c = s - (s / C) * C;
        const size_t base = (size_t)s * (HW * HW);

        if (tid < 13) {
            ((float*)(sm + OFF_KH))[tid] = gkh[c * 13 + tid];
            ((float*)(sm + OFF_KW))[tid] = gkw[c * 13 + tid];
        }

        // ---- load + hi/lo convert Q, K, V ----
        const float4* q4 = (const float4*)(gq + base) + (lr0 * 24 + lc0 / 4);
        const float4* k4 = (const float4*)(gk + base) + (lr0 * 24 + lc0 / 4);
        const float4* v4 = (const float4*)(gv + base) + (lr0 * 24 + lc0 / 4);
        #pragma unroll
        for (int it = 0; it < 6; it++) {
            const u32 ad = lad0 + (u32)(it * 16 * RSB);
            const int go = it * 384;           // 16 rows * 24 float4
            u32 h0, l0, h1, l1;
            float4 x;
            x = q4[go];
            cvt2(x.x, x.y, h0, l0); cvt2(x.z, x.w, h1, l1);
            *(ull*)(sm + T_QH + ad) = (ull)h0 | ((ull)h1 << 32);
            *(ull*)(sm + T_QL + ad) = (ull)l0 | ((ull)l1 << 32);
            x = k4[go];
            cvt2(x.x, x.y, h0, l0); cvt2(x.z, x.w, h1, l1);
            *(ull*)(sm + T_KH + ad) = (ull)h0 | ((ull)h1 << 32);
            *(ull*)(sm + T_KL + ad) = (ull)l0 | ((ull)l1 << 32);
            x = v4[go];
            cvt2(x.x, x.y, h0, l0); cvt2(x.z, x.w, h1, l1);
            *(ull*)(sm + T_VH + ad) = (ull)h0 | ((ull)h1 << 32);
            *(ull*)(sm + T_VL + ad) = (ull)l0 | ((ull)l1 << 32);
        }
        __syncthreads();

        // ---- L2 prefetch for the next slice this CTA will process ----
        if (s + NSM < slices && tid < 288) {
            const size_t nb = (size_t)(s + NSM) * (HW * HW);
            const char* pq = (const char*)(gq + nb) + tid * 128;
            const char* pk = (const char*)(gk + nb) + tid * 128;
            const char* pv = (const char*)(gv + nb) + tid * 128;
            pref_l2(pq); pref_l2(pk); pref_l2(pv);
        }

        // ============ Phase 1: warps 0-5 -> A1 rows; warps 6-11 -> A2 rows ===
        {
            float acc[12][4];
            const int m0 = (wid < 6 ? wid : wid - 6) * 16;
            const float* band;
            u32 dH, dL;
            if (wid < 6) {
                gemm_wt<0, 0, 12>(acc, sb + T_QH, sb + T_QL, sb + T_KH, sb + T_KL, m0, 0, lane);
                band = (const float*)(sm + OFF_KH);
                dH = sb + T_A1H; dL = sb + T_A1L;
            } else {
                gemm_wt<1, 1, 12>(acc, sb + T_QH, sb + T_QL, sb + T_KH, sb + T_KL, m0, 0, lane);
                band = (const float*)(sm + OFF_KW);
                dH = sb + T_A2H; dL = sb + T_A2L;
            }
            #pragma unroll
            for (int rh = 0; rh < 2; rh++) {
                const int row = m0 + (lane >> 2) + 8 * rh;
                float mx = -1e30f;
                #pragma unroll
                for (int nt = 0; nt < 12; nt++)
                    mx = fmaxf(mx, fmaxf(acc[nt][2 * rh], acc[nt][2 * rh + 1]));
                mx = fmaxf(mx, __shfl_xor_sync(0xffffffffu, mx, 1));
                mx = fmaxf(mx, __shfl_xor_sync(0xffffffffu, mx, 2));
                float su = 0.f;
                #pragma unroll
                for (int nt = 0; nt < 12; nt++)
                    #pragma unroll
                    for (int e = 0; e < 2; e++) {
                        float ev = __expf(acc[nt][2 * rh + e] - mx);
                        acc[nt][2 * rh + e] = ev;
                        su += ev;
                    }
                su += __shfl_xor_sync(0xffffffffu, su, 1);
                su += __shfl_xor_sync(0xffffffffu, su, 2);
                const float inv = 1.0f / su;
                #pragma unroll
                for (int nt = 0; nt < 12; nt++) {
                    const int col = nt * 8 + (lane & 3) * 2;
                    u32 b0 = (u32)(col - row + 6), b1 = (u32)(col + 1 - row + 6);
                    float x0 = fmaf(acc[nt][2 * rh + 0], inv, b0 < 13u ? band[b0] : 0.f);
                    float x1 = fmaf(acc[nt][2 * rh + 1], inv, b1 < 13u ? band[b1] : 0.f);
                    u32 h, l;
                    cvt2(x0, x1, h, l);
                    const u32 ad = (u32)(row * RSB + col * 2);
                    *(u32*)((char*)sm + (dH - sb) + ad) = h;
                    *(u32*)((char*)sm + (dL - sb) + ad) = l;
                }
            }
        }
        __syncthreads();

        // ============ Phase 2: GEMM2 V1 = A1 @ V  (12 warps, tile 16x48) =====
        const int m0b = (wid >> 1) * 16;
        const int n0b = (wid & 1) * 48;
        {
            float acc[6][4];
            gemm_wt<0, 1, 6>(acc, sb + T_A1H, sb + T_A1L, sb + T_VH, sb + T_VL, m0b, n0b, lane);
            #pragma unroll
            for (int rh = 0; rh < 2; rh++) {
                const int row = m0b + (lane >> 2) + 8 * rh;
                #pragma unroll
                for (int nt = 0; nt < 6; nt++) {
                    const int col = n0b + nt * 8 + (lane & 3) * 2;
                    u32 h, l;
                    cvt2(acc[nt][2 * rh + 0], acc[nt][2 * rh + 1], h, l);
                    const u32 ad = (u32)(row * RSB + col * 2);
                    *(u32*)(sm + T_V1H + ad) = h;
                    *(u32*)(sm + T_V1L + ad) = l;
                }
            }
        }
        __syncthreads();

        // ============ Phase 3: GEMM4 Out = V1 @ A2^T  (tile 16x48) ===========
        {
            float acc[6][4];
            gemm_wt<0, 0, 6>(acc, sb + T_V1H, sb + T_V1L, sb + T_A2H, sb + T_A2L, m0b, n0b, lane);
            float* op = gout + base;
            #pragma unroll
            for (int rh = 0; rh < 2; rh++) {
                const int row = m0b + (lane >> 2) + 8 * rh;
                #pragma unroll
                for (int nt = 0; nt < 6; nt++) {
                    const int col = n0b + nt * 8 + (lane & 3) * 2;
                    *(float2*)(op + row * HW + col) =
                        make_float2(acc[nt][2 * rh + 0], acc[nt][2 * rh + 1]);
                }
            }
        }
        __syncthreads();   // tiles dead; safe to overwrite next iteration
    }
}

extern "C" void kernel_launch(void* const* d_in, const int* in_sizes, int n_in,
                              void* d_out, int out_size)
{
    const float* q  = (const float*)d_in[0];
    const float* k  = (const float*)d_in[1];
    const float* v  = (const float*)d_in[2];
    const float* kh = (const float*)d_in[3];
    const float* kw = (const float*)d_in[4];
    float* out = (float*)d_out;

    const int slices = in_sizes[0] / (HW * HW);   // B*C = 2048
    const int C      = in_sizes[3] / 13;          // 256

    cudaFuncSetAttribute(axial_attn_hmma5,
                         cudaFuncAttributeMaxDynamicSharedMemorySize, SMEM_TOTAL);
    axial_attn_hmma5<<<NSM, TPB, SMEM_TOTAL>>>(q, k, v, kh, kw, out, C, slices);
}

// round 17
// speedup vs baseline: 1.1075x; 1.0105x over previous
#include <cuda_runtime.h>
#include <cuda_bf16.h>

typedef unsigned int u32;
typedef unsigned long long ull;

#define HW   96
#define TPB  384
#define NSM  148              // persistent grid size
#define LDB  104              // bf16 elems per tile row (stride 208 B, conflict-free ldmatrix)
#define RSB  (LDB * 2)        // 208 bytes
#define TILE_B (HW * RSB)     // 19968 B per tile

// ---- smem byte offsets ----
#define OFF_KH   0            // 13 floats
#define OFF_KW   64           // 13 floats
#define OFF_RMAX 128          // [2 sides][96 rows][2 halves] f32 = 1536 B
#define OFF_RSUM (OFF_RMAX + 1536)
#define T_BASE   (OFF_RSUM + 1536)          // 3200
#define T_QH   (T_BASE + 0 * TILE_B)
#define T_QL   (T_BASE + 1 * TILE_B)
#define T_KH   (T_BASE + 2 * TILE_B)
#define T_KL   (T_BASE + 3 * TILE_B)
#define T_VH   (T_BASE + 4 * TILE_B)
#define T_VL   (T_BASE + 5 * TILE_B)
#define T_A1H  (T_BASE + 6 * TILE_B)
#define T_A1L  (T_BASE + 7 * TILE_B)
#define T_A2H  (T_BASE + 8 * TILE_B)
#define T_A2L  (T_BASE + 9 * TILE_B)
#define SMEM_TOTAL (T_BASE + 10 * TILE_B)   // 202880 B
// V1 reuses Q tiles (Q dead after phase 1):
#define T_V1H T_QH
#define T_V1L T_QL

// ---------------- PTX wrappers ----------------
__device__ __forceinline__ u32 s2u(const void* p) {
    u32 a;
    asm("{ .reg .u64 t; cvta.to.shared.u64 t, %1; cvt.u32.u64 %0, t; }" : "=r"(a) : "l"(p));
    return a;
}
template<int TR>
__device__ __forceinline__ void ldsm4(u32 addr, u32* r) {
    if (TR)
        asm volatile("ldmatrix.sync.aligned.m8n8.x4.trans.shared.b16 {%0,%1,%2,%3}, [%4];"
                     : "=r"(r[0]), "=r"(r[1]), "=r"(r[2]), "=r"(r[3]) : "r"(addr));
    else
        asm volatile("ldmatrix.sync.aligned.m8n8.x4.shared.b16 {%0,%1,%2,%3}, [%4];"
                     : "=r"(r[0]), "=r"(r[1]), "=r"(r[2]), "=r"(r[3]) : "r"(addr));
}
template<int TR>
__device__ __forceinline__ void ldsm2(u32 addr, u32* r) {
    if (TR)
        asm volatile("ldmatrix.sync.aligned.m8n8.x2.trans.shared.b16 {%0,%1}, [%2];"
                     : "=r"(r[0]), "=r"(r[1]) : "r"(addr));
    else
        asm volatile("ldmatrix.sync.aligned.m8n8.x2.shared.b16 {%0,%1}, [%2];"
                     : "=r"(r[0]), "=r"(r[1]) : "r"(addr));
}
__device__ __forceinline__ void mma16816(float* c, const u32* a, const u32* b) {
    asm volatile("mma.sync.aligned.m16n8k16.row.col.f32.bf16.bf16.f32 "
                 "{%0,%1,%2,%3}, {%4,%5,%6,%7}, {%8,%9}, {%0,%1,%2,%3};"
                 : "+f"(c[0]), "+f"(c[1]), "+f"(c[2]), "+f"(c[3])
                 : "r"(a[0]), "r"(a[1]), "r"(a[2]), "r"(a[3]), "r"(b[0]), "r"(b[1]));
}
__device__ __forceinline__ void pref_l2(const void* p) {
    asm volatile("prefetch.global.L2 [%0];" :: "l"(p));
}

// ---- hi/lo bf16 split: pack pair (x0,x1) -> hi u32, lo u32 ----
__device__ __forceinline__ void cvt2(float x0, float x1, u32& h, u32& l) {
    asm("cvt.rn.bf16x2.f32 %0, %1, %2;" : "=r"(h) : "f"(x1), "f"(x0));
    float h0 = __uint_as_float(h << 16);
    float h1 = __uint_as_float(h & 0xffff0000u);
    asm("cvt.rn.bf16x2.f32 %0, %1, %2;" : "=r"(l) : "f"(x1 - h1), "f"(x0 - h0));
}

// ---- warp-tile GEMM (16*MT) x (8*NT) x 96, BF16x3, single-buffered ----
// Pass order: ldsm Bh -> Ah*Bh -> ldsm Bl -> Al*Bh -> Ah*Bl
// (Bl latency hidden behind the Al*Bh pass; proven in R10/R13.)
template<int TA, int TB, int MT, int NT>
__device__ __forceinline__ void gemm_wt(float acc[MT][NT][4],
                                        u32 aH, u32 aL, u32 bH, u32 bL,
                                        int m0, int n0, int lane)
{
    constexpr int G4 = NT / 2;
    constexpr int H2 = NT & 1;

    #pragma unroll
    for (int mt = 0; mt < MT; mt++)
        #pragma unroll
        for (int nt = 0; nt < NT; nt++)
            #pragma unroll
            for (int e = 0; e < 4; e++) acc[mt][nt][e] = 0.f;

    u32 aad[MT];
    #pragma unroll
    for (int mt = 0; mt < MT; mt++) {
        int ra, ca;
        if (TA) { ra = (lane & 7) + ((lane >> 4) & 1) * 8; ca = m0 + mt * 16 + ((lane >> 3) & 1) * 8; }
        else    { ra = m0 + mt * 16 + (lane & 7) + ((lane >> 3) & 1) * 8; ca = ((lane >> 4) & 1) * 8; }
        aad[mt] = (u32)(ra * RSB + ca * 2);
    }
    const u32 astep = TA ? (u32)(16 * RSB) : 32u;

    u32 bad[G4 + H2];
    #pragma unroll
    for (int p = 0; p < G4; p++) {
        int rb, cb;
        if (TB) { rb = (lane & 7) + ((lane >> 3) & 1) * 8; cb = n0 + p * 16 + ((lane >> 4) & 1) * 8; }
        else    { rb = n0 + p * 16 + (lane & 7) + ((lane >> 4) & 1) * 8; cb = ((lane >> 3) & 1) * 8; }
        bad[p] = (u32)(rb * RSB + cb * 2);
    }
    if (H2) {
        const int L = lane & 15;
        int rb, cb;
        if (TB) { rb = (L & 7) + ((L >> 3) & 1) * 8; cb = n0 + (NT - 1) * 8; }
        else    { rb = n0 + (NT - 1) * 8 + (L & 7); cb = ((L >> 3) & 1) * 8; }
        bad[G4] = (u32)(rb * RSB + cb * 2);
    }
    const u32 bstep = TB ? (u32)(16 * RSB) : 32u;

    #pragma unroll
    for (int kk = 0; kk < HW; kk += 16) {
        u32 Ah[MT][4], Al[MT][4];
        #pragma unroll
        for (int mt = 0; mt < MT; mt++) {
            ldsm4<TA>(aH + aad[mt], Ah[mt]);
            ldsm4<TA>(aL + aad[mt], Al[mt]);
        }

        u32 Bh[NT][2], Bl[NT][2];
        #pragma unroll
        for (int p = 0; p < G4; p++) {
            u32 t[4];
            ldsm4<TB>(bH + bad[p], t);
            Bh[2 * p][0] = t[0]; Bh[2 * p][1] = t[1];
            Bh[2 * p + 1][0] = t[2]; Bh[2 * p + 1][1] = t[3];
        }
        if (H2) ldsm2<TB>(bH + bad[G4], Bh[NT - 1]);

        #pragma unroll
        for (int mt = 0; mt < MT; mt++)
            #pragma unroll
            for (int nt = 0; nt < NT; nt++) mma16816(acc[mt][nt], Ah[mt], Bh[nt]);

        #pragma unroll
        for (int p = 0; p < G4; p++) {
            u32 t[4];
            ldsm4<TB>(bL + bad[p], t);
            Bl[2 * p][0] = t[0]; Bl[2 * p][1] = t[1];
            Bl[2 * p + 1][0] = t[2]; Bl[2 * p + 1][1] = t[3];
        }
        if (H2) ldsm2<TB>(bL + bad[G4], Bl[NT - 1]);

        #pragma unroll
        for (int mt = 0; mt < MT; mt++)
            #pragma unroll
            for (int nt = 0; nt < NT; nt++) mma16816(acc[mt][nt], Al[mt], Bh[nt]);
        #pragma unroll
        for (int mt = 0; mt < MT; mt++)
            #pragma unroll
            for (int nt = 0; nt < NT; nt++) mma16816(acc[mt][nt], Ah[mt], Bl[nt]);

        #pragma unroll
        for (int mt = 0; mt < MT; mt++) aad[mt] += astep;
        #pragma unroll
        for (int p = 0; p < G4 + H2; p++) bad[p] += bstep;
    }
}

__global__ void __launch_bounds__(TPB, 1)
axial_attn_hmma7(const float* __restrict__ gq, const float* __restrict__ gk,
                 const float* __restrict__ gv, const float* __restrict__ gkh,
                 const float* __restrict__ gkw, float* __restrict__ gout,
                 int C, int slices)
{
    extern __shared__ char sm[];
    const u32 sb = s2u(sm);
    const int tid  = threadIdx.x;
    const int lane = tid & 31;
    const int wid  = tid >> 5;        // 0..11

    // load-loop index math: 384 threads, 24 float4 per row -> row advances 16/iter
    const int lr0 = tid / 24;
    const int lc0 = (tid - lr0 * 24) * 4;
    const u32 lad0 = (u32)(lr0 * RSB + lc0 * 2);

    // phase-1 tiling: 32x48 warp tiles; side 0 = S1 (warps 0-5), side 1 = S2
    const int side = (wid < 6) ? 0 : 1;
    const int sidx = side ? wid - 6 : wid;
    const int m0a  = (sidx >> 1) * 32;
    const int n0a  = (sidx & 1) * 48;
    // phase-2/3 tiling: 32x24 warp tiles
    const int m0b = (wid >> 2) * 32;
    const int n0b = (wid & 3) * 24;

    for (int s = blockIdx.x; s < slices; s += NSM) {
        const int c = s - (s / C) * C;
        const size_t base = (size_t)s * (HW * HW);

        if (tid < 13) {
            ((float*)(sm + OFF_KH))[tid] = gkh[c * 13 + tid];
            ((float*)(sm + OFF_KW))[tid] = gkw[c * 13 + tid];
        }

        // ---- load + hi/lo convert Q, K, V ----
        const float4* q4 = (const float4*)(gq + base) + (lr0 * 24 + lc0 / 4);
        const float4* k4 = (const float4*)(gk + base) + (lr0 * 24 + lc0 / 4);
        const float4* v4 = (const float4*)(gv + base) + (lr0 * 24 + lc0 / 4);
        #pragma unroll
        for (int it = 0; it < 6; it++) {
            const u32 ad = lad0 + (u32)(it * 16 * RSB);
            const int go = it * 384;
            u32 h0, l0, h1, l1;
            float4 x;
            x = q4[go];
            cvt2(x.x, x.y, h0, l0); cvt2(x.z, x.w, h1, l1);
            *(ull*)(sm + T_QH + ad) = (ull)h0 | ((ull)h1 << 32);
            *(ull*)(sm + T_QL + ad) = (ull)l0 | ((ull)l1 << 32);
            x = k4[go];
            cvt2(x.x, x.y, h0, l0); cvt2(x.z, x.w, h1, l1);
            *(ull*)(sm + T_KH + ad) = (ull)h0 | ((ull)h1 << 32);
            *(ull*)(sm + T_KL + ad) = (ull)l0 | ((ull)l1 << 32);
            x = v4[go];
            cvt2(x.x, x.y, h0, l0); cvt2(x.z, x.w, h1, l1);
            *(ull*)(sm + T_VH + ad) = (ull)h0 | ((ull)h1 << 32);
            *(ull*)(sm + T_VL + ad) = (ull)l0 | ((ull)l1 << 32);
        }
        __syncthreads();

        // ---- L2 prefetch for the next slice this CTA will process ----
        if (s + NSM < slices && tid < 288) {
            const size_t nb = (size_t)(s + NSM) * (HW * HW);
            pref_l2((const char*)(gq + nb) + tid * 128);
            pref_l2((const char*)(gk + nb) + tid * 128);
            pref_l2((const char*)(gv + nb) + tid * 128);
        }

        // ============ Phase 1: S1 (warps 0-5) / S2 (warps 6-11), 32x48 tiles =
        {
            float acc[2][6][4];
            if (side == 0)
                gemm_wt<0, 0, 2, 6>(acc, sb + T_QH, sb + T_QL, sb + T_KH, sb + T_KL, m0a, n0a, lane);
            else
                gemm_wt<1, 1, 2, 6>(acc, sb + T_QH, sb + T_QL, sb + T_KH, sb + T_KL, m0a, n0a, lane);

            float* RMAX = (float*)(sm + OFF_RMAX);
            float* RSUM = (float*)(sm + OFF_RSUM);
            const int ni = sidx & 1;

            // partial row max over this warp's 12 cols
            #pragma unroll
            for (int mt = 0; mt < 2; mt++)
                #pragma unroll
                for (int rh = 0; rh < 2; rh++) {
                    float v = -1e30f;
                    #pragma unroll
                    for (int nt = 0; nt < 6; nt++)
                        v = fmaxf(v, fmaxf(acc[mt][nt][2 * rh], acc[mt][nt][2 * rh + 1]));
                    v = fmaxf(v, __shfl_xor_sync(0xffffffffu, v, 1));
                    v = fmaxf(v, __shfl_xor_sync(0xffffffffu, v, 2));
                    if ((lane & 3) == 0) {
                        const int row = m0a + mt * 16 + (lane >> 2) + 8 * rh;
                        RMAX[(side * 96 + row) * 2 + ni] = v;
                    }
                }
            __syncthreads();

            // exp + partial row sum
            #pragma unroll
            for (int mt = 0; mt < 2; mt++)
                #pragma unroll
                for (int rh = 0; rh < 2; rh++) {
                    const int row = m0a + mt * 16 + (lane >> 2) + 8 * rh;
                    const float* rm = RMAX + (side * 96 + row) * 2;
                    const float gm = fmaxf(rm[0], rm[1]);
                    float su = 0.f;
                    #pragma unroll
                    for (int nt = 0; nt < 6; nt++)
                        #pragma unroll
                        for (int e = 0; e < 2; e++) {
                            float ev = __expf(acc[mt][nt][2 * rh + e] - gm);
                            acc[mt][nt][2 * rh + e] = ev;
                            su += ev;
                        }
                    su += __shfl_xor_sync(0xffffffffu, su, 1);
                    su += __shfl_xor_sync(0xffffffffu, su, 2);
                    if ((lane & 3) == 0)
                        RSUM[(side * 96 + row) * 2 + ni] = su;
                }
            __syncthreads();

            // normalize + band -> bf16 hi/lo A tile
            const float* band = (const float*)(sm + (side ? OFF_KW : OFF_KH));
            const u32 dH = side ? (u32)T_A2H : (u32)T_A1H;
            const u32 dL = side ? (u32)T_A2L : (u32)T_A1L;
            #pragma unroll
            for (int mt = 0; mt < 2; mt++)
                #pragma unroll
                for (int rh = 0; rh < 2; rh++) {
                    const int row = m0a + mt * 16 + (lane >> 2) + 8 * rh;
                    const float* rs = RSUM + (side * 96 + row) * 2;
                    const float inv = 1.0f / (rs[0] + rs[1]);
                    #pragma unroll
                    for (int nt = 0; nt < 6; nt++) {
                        const int col = n0a + nt * 8 + (lane & 3) * 2;
                        u32 b0 = (u32)(col - row + 6), b1 = (u32)(col + 1 - row + 6);
                        float x0 = fmaf(acc[mt][nt][2 * rh + 0], inv, b0 < 13u ? band[b0] : 0.f);
                        float x1 = fmaf(acc[mt][nt][2 * rh + 1], inv, b1 < 13u ? band[b1] : 0.f);
                        u32 h, l;
                        cvt2(x0, x1, h, l);
                        const u32 ad = (u32)(row * RSB + col * 2);
                        *(u32*)(sm + dH + ad) = h;
                        *(u32*)(sm + dL + ad) = l;
                    }
                }
        }
        __syncthreads();

        // ============ Phase 2: V1 = A1 @ V  (32x24 tiles, B=V trans) =========
        {
            float acc[2][3][4];
            gemm_wt<0, 1, 2, 3>(acc, sb + T_A1H, sb + T_A1L, sb + T_VH, sb + T_VL, m0b, n0b, lane);
            #pragma unroll
            for (int mt = 0; mt < 2; mt++)
                #pragma unroll
                for (int rh = 0; rh < 2; rh++) {
                    const int row = m0b + mt * 16 + (lane >> 2) + 8 * rh;
                    #pragma unroll
                    for (int nt = 0; nt < 3; nt++) {
                        const int col = n0b + nt * 8 + (lane & 3) * 2;
                        u32 h, l;
                        cvt2(acc[mt][nt][2 * rh + 0], acc[mt][nt][2 * rh + 1], h, l);
                        const u32 ad = (u32)(row * RSB + col * 2);
                        *(u32*)(sm + T_V1H + ad) = h;
                        *(u32*)(sm + T_V1L + ad) = l;
                    }
                }
        }
        __syncthreads();

        // ============ Phase 3: Out = V1 @ A2^T  (32x24 tiles) ================
        {
            float acc[2][3][4];
            gemm_wt<0, 0, 2, 3>(acc, sb + T_V1H, sb + T_V1L, sb + T_A2H, sb + T_A2L, m0b, n0b, lane);
            float* op = gout + base;
            #pragma unroll
            for (int mt = 0; mt < 2; mt++)
                #pragma unroll
                for (int rh = 0; rh < 2; rh++) {
                    const int row = m0b + mt * 16 + (lane >> 2) + 8 * rh;
                    #pragma unroll
                    for (int nt = 0; nt < 3; nt++) {
                        const int col = n0b + nt * 8 + (lane & 3) * 2;
                        *(float2*)(op + row * HW + col) =
                            make_float2(acc[mt][nt][2 * rh + 0], acc[mt][nt][2 * rh + 1]);
                    }
                }
        }
        __syncthreads();   // tiles dead; safe to overwrite next iteration
    }
}

extern "C" void kernel_launch(void* const* d_in, const int* in_sizes, int n_in,
                              void* d_out, int out_size)
{
    const float* q  = (const float*)d_in[0];
    const float* k  = (const float*)d_in[1];
    const float* v  = (const float*)d_in[2];
    const float* kh = (const float*)d_in[3];
    const float* kw = (const float*)d_in[4];
    float* out = (float*)d_out;

    const int slices = in_sizes[0] / (HW * HW);   // B*C = 2048
    const int C      = in_sizes[3] / 13;          // 256

    cudaFuncSetAttribute(axial_attn_hmma7,
                         cudaFuncAttributeMaxDynamicSharedMemorySize, SMEM_TOTAL);
    axial_attn_hmma7<<<NSM, TPB, SMEM_TOTAL>>>(q, k, v, kh, kw, out, C, slices);
}